// round 1
// baseline (speedup 1.0000x reference)
#include <cuda_runtime.h>
#include <cuda_bf16.h>

#define NN 10
#define DD 64
#define BATCH 65536

// act_f = x @ g_M[f] + g_dv[f]
__device__ float g_M[NN][DD][DD];
__device__ float g_dv[NN][DD];
__device__ unsigned int g_cnt[16];   // per-step barrier counters (zero-init; reset by gemm kernel)

// ---------------------------------------------------------------------------
// Kernel 1: collapse the DAG into (M_9, d_9).
// Grid: 65 blocks x 256 threads. Blocks 0..63 compute M_t (8x8 tile each,
// 4-way k-split per element); block 64 computes the bias chain d_t.
// Steps t=1..9 separated by a device-wide counting barrier (8 barriers).
// ---------------------------------------------------------------------------
__global__ __launch_bounds__(256) void precompute_kernel(const float* __restrict__ W,
                                                         const float* __restrict__ B) {
    const int tid = threadIdx.x;
    const int bi  = blockIdx.x;
    __shared__ float red[256];
    const int s  = tid >> 6;     // k-segment 0..3
    const int e  = tid & 63;     // element within block
    const int k0 = s * 16;

    if (bi < 64) {
        const int d = (bi >> 3) * 8 + (e >> 3);
        const int h = (bi & 7) * 8 + (e & 7);
        for (int t = 1; t <= 9; ++t) {
            float acc = 0.f;
            // f = 0 term: M_0 = I  ->  contributes W[0,t,d,h]
            if (s == 0) acc = W[((0 * NN + t) * DD + d) * DD + h];
            for (int f = 1; f < t; ++f) {
                const float* Mf = &g_M[f][d][k0];
                const float* Wf = &W[((f * NN + t) * DD + k0) * DD + h];
                #pragma unroll
                for (int k = 0; k < 16; ++k)
                    acc += Mf[k] * Wf[k * DD];
            }
            red[tid] = acc;
            __syncthreads();
            if (s == 0)
                g_M[t][d][h] = red[e] + red[64 + e] + red[128 + e] + red[192 + e];
            if (t == 9) break;
            // ---- device-wide barrier (release: fence before arrive) ----
            __threadfence();
            __syncthreads();
            if (tid == 0) {
                atomicAdd(&g_cnt[t], 1u);
                while (atomicAdd(&g_cnt[t], 0u) < 65u) { __nanosleep(32); }
            }
            __syncthreads();
        }
    } else {
        // bias chain: d_t[h] = sum_f b[f,t,h] + sum_{f>=1} d_f @ W[f,t]
        const int h = e;
        for (int t = 1; t <= 9; ++t) {
            float acc = 0.f;
            if (s == 0) {
                for (int f = 0; f < t; ++f)
                    acc += B[(f * NN + t) * DD + h];
            }
            for (int f = 1; f < t; ++f) {
                const float* dvf = &g_dv[f][k0];
                const float* Wf  = &W[((f * NN + t) * DD + k0) * DD + h];
                #pragma unroll
                for (int k = 0; k < 16; ++k)
                    acc += dvf[k] * Wf[k * DD];
            }
            red[tid] = acc;
            __syncthreads();
            if (s == 0)
                g_dv[t][h] = red[e] + red[64 + e] + red[128 + e] + red[192 + e];
            if (t == 9) break;
            __threadfence();
            __syncthreads();
            if (tid == 0) {
                atomicAdd(&g_cnt[t], 1u);
                while (atomicAdd(&g_cnt[t], 0u) < 65u) { __nanosleep(32); }
            }
            __syncthreads();
        }
    }
}

// ---------------------------------------------------------------------------
// Kernel 2: out = x @ M_9 + d_9.
// Grid: 256 blocks x 256 threads, 256 rows/block. x tile staged transposed in
// shared (conflict-free scalar STS, LDS.128 reads), M_9 in shared.
// Per thread: 8 rows x 8 cols register tile -> 64 FFMA per 4 LDS.128.
// Also resets the barrier counters for the next graph replay.
// ---------------------------------------------------------------------------
__global__ __launch_bounds__(256) void gemm_kernel(const float* __restrict__ x,
                                                   float* __restrict__ out) {
    extern __shared__ float sh[];
    float* xT  = sh;                   // [64][256]
    float* Ms  = sh + 64 * 256;        // [64][64]
    float* dvs = Ms + 64 * 64;         // [64]
    const int tid = threadIdx.x;
    const int R0  = blockIdx.x * 256;

    if (blockIdx.x == 0 && tid < 16) g_cnt[tid] = 0u;   // reset barriers for next launch

    // stage x rows transposed: thread tid owns global row R0+tid
    const float4* xrow = reinterpret_cast<const float4*>(x + (size_t)(R0 + tid) * DD);
    #pragma unroll
    for (int i = 0; i < 16; ++i) {
        float4 v = xrow[i];
        xT[(4 * i + 0) * 256 + tid] = v.x;
        xT[(4 * i + 1) * 256 + tid] = v.y;
        xT[(4 * i + 2) * 256 + tid] = v.z;
        xT[(4 * i + 3) * 256 + tid] = v.w;
    }
    // stage M_9 (4096 floats = 1024 float4)
    const float4* M4  = reinterpret_cast<const float4*>(&g_M[9][0][0]);
    float4*       Ms4 = reinterpret_cast<float4*>(Ms);
    #pragma unroll
    for (int i = 0; i < 4; ++i) Ms4[tid + 256 * i] = M4[tid + 256 * i];
    if (tid < 64) dvs[tid] = g_dv[9][tid];
    __syncthreads();

    const int rg = tid >> 3;  // 0..31 -> rows rg*8..rg*8+7
    const int cg = tid & 7;   // 0..7  -> cols cg*8..cg*8+7
    float acc[64];
    #pragma unroll
    for (int i = 0; i < 64; ++i) acc[i] = 0.f;

    #pragma unroll 2
    for (int d = 0; d < 64; ++d) {
        float4 a0 = *reinterpret_cast<const float4*>(&xT[d * 256 + rg * 8]);
        float4 a1 = *reinterpret_cast<const float4*>(&xT[d * 256 + rg * 8 + 4]);
        float4 b0 = *reinterpret_cast<const float4*>(&Ms[d * 64 + cg * 8]);
        float4 b1 = *reinterpret_cast<const float4*>(&Ms[d * 64 + cg * 8 + 4]);
        float xa[8] = {a0.x, a0.y, a0.z, a0.w, a1.x, a1.y, a1.z, a1.w};
        float mb[8] = {b0.x, b0.y, b0.z, b0.w, b1.x, b1.y, b1.z, b1.w};
        #pragma unroll
        for (int i = 0; i < 8; ++i)
            #pragma unroll
            for (int j = 0; j < 8; ++j)
                acc[i * 8 + j] += xa[i] * mb[j];
    }

    float dvr[8];
    #pragma unroll
    for (int j = 0; j < 8; ++j) dvr[j] = dvs[cg * 8 + j];

    #pragma unroll
    for (int i = 0; i < 8; ++i) {
        const int row = R0 + rg * 8 + i;
        float4 o0 = make_float4(acc[i * 8 + 0] + dvr[0], acc[i * 8 + 1] + dvr[1],
                                acc[i * 8 + 2] + dvr[2], acc[i * 8 + 3] + dvr[3]);
        float4 o1 = make_float4(acc[i * 8 + 4] + dvr[4], acc[i * 8 + 5] + dvr[5],
                                acc[i * 8 + 6] + dvr[6], acc[i * 8 + 7] + dvr[7]);
        float4* orow = reinterpret_cast<float4*>(out + (size_t)row * DD);
        orow[cg * 2 + 0] = o0;
        orow[cg * 2 + 1] = o1;
    }
}

extern "C" void kernel_launch(void* const* d_in, const int* in_sizes, int n_in,
                              void* d_out, int out_size) {
    const float* x = (const float*)d_in[0];
    const float* W = (const float*)d_in[1];
    const float* b = (const float*)d_in[2];
    float* out = (float*)d_out;

    const int smem_bytes = (64 * 256 + 64 * 64 + 64) * sizeof(float);  // 82176
    cudaFuncSetAttribute(gemm_kernel, cudaFuncAttributeMaxDynamicSharedMemorySize, smem_bytes);

    precompute_kernel<<<65, 256>>>(W, b);
    gemm_kernel<<<256, 256, smem_bytes>>>(x, out);
}

// round 2
// speedup vs baseline: 1.1423x; 1.1423x over previous
#include <cuda_runtime.h>
#include <cuda_bf16.h>

#define NN 10
#define DD 64

__device__ float g_M9[DD][DD];   // out = x @ g_M9 + g_dv9
__device__ float g_dv9[DD];

// ---------------------------------------------------------------------------
// Kernel 1: collapse the DAG into (M_9, d_9) with NO grid-wide sync.
// Row decomposition: M_t[d,:] = W[0,t][d,:] + sum_{f=1}^{t-1} M_f[d,:] @ W[f,t].
// Block d (0..63) carries row d of all M_t in shared memory through the chain.
// Block 64 carries the bias chain d_t (a single 64-vector) the same way.
// 256 threads: s = tid>>6 is a 16-wide k-segment, h = tid&63 the output column.
// ---------------------------------------------------------------------------
__global__ __launch_bounds__(256) void precompute_kernel(const float* __restrict__ W,
                                                         const float* __restrict__ B) {
    __shared__ float row[NN][DD];   // row[f][:] = row d of M_f   (or d_f for bias block)
    __shared__ float red[256];
    const int tid = threadIdx.x;
    const int bi  = blockIdx.x;
    const int s   = tid >> 6;      // k-segment 0..3
    const int h   = tid & 63;      // output column
    const int k0  = s * 16;

    if (bi < 64) {
        const int d = bi;
        for (int t = 1; t <= 9; ++t) {
            // f = 0 term: M_0 = I -> contributes W[0,t][d,h]
            float acc = (s == 0) ? W[((size_t)t * DD + d) * DD + h] : 0.f;
            for (int f = 1; f < t; ++f) {
                const float* Wf = &W[(((size_t)f * NN + t) * DD + k0) * DD + h];
                const float* Mf = &row[f][k0];
                #pragma unroll
                for (int k = 0; k < 16; ++k)
                    acc += Mf[k] * Wf[(size_t)k * DD];
            }
            red[tid] = acc;
            __syncthreads();
            if (s == 0) {
                float v = red[h] + red[64 + h] + red[128 + h] + red[192 + h];
                row[t][h] = v;
                if (t == 9) g_M9[d][h] = v;
            }
            __syncthreads();
        }
    } else {
        // bias chain: d_t[h] = sum_{f<t} b[f,t][h] + sum_{f=1}^{t-1} d_f @ W[f,t][:,h]
        for (int t = 1; t <= 9; ++t) {
            float acc = 0.f;
            if (s == 0) {
                for (int f = 0; f < t; ++f)
                    acc += B[((size_t)f * NN + t) * DD + h];
            }
            for (int f = 1; f < t; ++f) {
                const float* Wf = &W[(((size_t)f * NN + t) * DD + k0) * DD + h];
                const float* df = &row[f][k0];
                #pragma unroll
                for (int k = 0; k < 16; ++k)
                    acc += df[k] * Wf[(size_t)k * DD];
            }
            red[tid] = acc;
            __syncthreads();
            if (s == 0) {
                float v = red[h] + red[64 + h] + red[128 + h] + red[192 + h];
                row[t][h] = v;
                if (t == 9) g_dv9[h] = v;
            }
            __syncthreads();
        }
    }
}

// ---------------------------------------------------------------------------
// Kernel 2: out = x @ M_9 + d_9.
// 256 blocks x 256 threads, 256 rows/block; x tile staged transposed in
// shared, M_9 in shared; 8x8 register tile per thread (64 FFMA / 4 LDS.128).
// launch_bounds(256,2) keeps regs <=128 so 2 blocks (16 warps) fit per SM.
// ---------------------------------------------------------------------------
__global__ __launch_bounds__(256, 2) void gemm_kernel(const float* __restrict__ x,
                                                      float* __restrict__ out) {
    extern __shared__ float sh[];
    float* xT  = sh;                   // [64][256]
    float* Ms  = sh + 64 * 256;        // [64][64]
    float* dvs = Ms + 64 * 64;         // [64]
    const int tid = threadIdx.x;
    const int R0  = blockIdx.x * 256;

    // stage x rows transposed: thread tid owns global row R0+tid
    const float4* xrow = reinterpret_cast<const float4*>(x + (size_t)(R0 + tid) * DD);
    #pragma unroll
    for (int i = 0; i < 16; ++i) {
        float4 v = xrow[i];
        xT[(4 * i + 0) * 256 + tid] = v.x;
        xT[(4 * i + 1) * 256 + tid] = v.y;
        xT[(4 * i + 2) * 256 + tid] = v.z;
        xT[(4 * i + 3) * 256 + tid] = v.w;
    }
    // stage M_9 (4096 floats = 1024 float4)
    const float4* M4  = reinterpret_cast<const float4*>(&g_M9[0][0]);
    float4*       Ms4 = reinterpret_cast<float4*>(Ms);
    #pragma unroll
    for (int i = 0; i < 4; ++i) Ms4[tid + 256 * i] = M4[tid + 256 * i];
    if (tid < 64) dvs[tid] = g_dv9[tid];
    __syncthreads();

    const int rg = tid >> 3;  // 0..31 -> rows rg*8..rg*8+7
    const int cg = tid & 7;   // 0..7  -> cols cg*8..cg*8+7
    float acc[64];
    #pragma unroll
    for (int i = 0; i < 64; ++i) acc[i] = 0.f;

    #pragma unroll 4
    for (int d = 0; d < 64; ++d) {
        float4 a0 = *reinterpret_cast<const float4*>(&xT[d * 256 + rg * 8]);
        float4 a1 = *reinterpret_cast<const float4*>(&xT[d * 256 + rg * 8 + 4]);
        float4 b0 = *reinterpret_cast<const float4*>(&Ms[d * 64 + cg * 8]);
        float4 b1 = *reinterpret_cast<const float4*>(&Ms[d * 64 + cg * 8 + 4]);
        float xa[8] = {a0.x, a0.y, a0.z, a0.w, a1.x, a1.y, a1.z, a1.w};
        float mb[8] = {b0.x, b0.y, b0.z, b0.w, b1.x, b1.y, b1.z, b1.w};
        #pragma unroll
        for (int i = 0; i < 8; ++i)
            #pragma unroll
            for (int j = 0; j < 8; ++j)
                acc[i * 8 + j] += xa[i] * mb[j];
    }

    float dvr[8];
    #pragma unroll
    for (int j = 0; j < 8; ++j) dvr[j] = dvs[cg * 8 + j];

    #pragma unroll
    for (int i = 0; i < 8; ++i) {
        const int row = R0 + rg * 8 + i;
        float4 o0 = make_float4(acc[i * 8 + 0] + dvr[0], acc[i * 8 + 1] + dvr[1],
                                acc[i * 8 + 2] + dvr[2], acc[i * 8 + 3] + dvr[3]);
        float4 o1 = make_float4(acc[i * 8 + 4] + dvr[4], acc[i * 8 + 5] + dvr[5],
                                acc[i * 8 + 6] + dvr[6], acc[i * 8 + 7] + dvr[7]);
        float4* orow = reinterpret_cast<float4*>(out + (size_t)row * DD);
        orow[cg * 2 + 0] = o0;
        orow[cg * 2 + 1] = o1;
    }
}

extern "C" void kernel_launch(void* const* d_in, const int* in_sizes, int n_in,
                              void* d_out, int out_size) {
    const float* x = (const float*)d_in[0];
    const float* W = (const float*)d_in[1];
    const float* b = (const float*)d_in[2];
    float* out = (float*)d_out;

    const int smem_bytes = (64 * 256 + 64 * 64 + 64) * sizeof(float);  // 82176
    cudaFuncSetAttribute(gemm_kernel, cudaFuncAttributeMaxDynamicSharedMemorySize, smem_bytes);

    precompute_kernel<<<65, 256>>>(W, b);
    gemm_kernel<<<256, 256, smem_bytes>>>(x, out);
}

// round 3
// speedup vs baseline: 1.5055x; 1.3180x over previous
#include <cuda_runtime.h>
#include <cuda_bf16.h>

#define NN 10
#define DD 64

__device__ float g_M9[DD][DD];   // out = x @ g_M9 + g_dv9
__device__ float g_dv9[DD];

// ---------------------------------------------------------------------------
// Kernel 1: collapse the DAG into (M_9, d_9). No grid sync.
// 17 blocks x 256 threads. Blocks 0..15 carry 4 rows (d = 4*bi..4*bi+3) of
// every M_t through the chain in shared memory:
//   M_t[d,:] = W[0,t][d,:] + sum_{f=1}^{t-1} M_f[d,:] @ W[f,t]
// Block 16 carries the bias chain d_t (augmented-row trick, r=0 active):
//   d_t = sum_{f<t} b[f,t] + sum_{f=1}^{t-1} d_f @ W[f,t]
// Thread (kk,hg): kk = tid>>4 owns k = 4kk..4kk+3, hg = tid&15 owns
// h = 4hg..4hg+3. W read via LDG.128; k-reduction through shared.
// ---------------------------------------------------------------------------
__global__ __launch_bounds__(256) void precompute_kernel(const float* __restrict__ W,
                                                         const float* __restrict__ B) {
    __shared__ __align__(16) float rowsh[NN][4][DD];  // rowsh[f][r][h]
    __shared__ __align__(16) float red[16][4][DD];    // red[kk][r][h]
    const int tid  = threadIdx.x;
    const int bi   = blockIdx.x;
    const bool bias = (bi == 16);
    const int d0   = bi * 4;
    const int kk   = tid >> 4;    // 0..15
    const int hg   = tid & 15;    // 0..15
    const int rr   = tid >> 6;    // reduction row 0..3
    const int hh   = tid & 63;    // reduction col 0..63

    // init rowsh[0]: identity rows for M-blocks, zeros for bias block
    rowsh[0][rr][hh] = (!bias && (d0 + rr == hh)) ? 1.f : 0.f;
    __syncthreads();

    for (int t = 1; t <= 9; ++t) {
        // prefetch the f=0 extra term for the reduction phase
        float extra = 0.f;
        if (!bias) {
            extra = W[((size_t)t * DD + (d0 + rr)) * DD + hh];          // W[0,t][d,h]
        } else if (rr == 0) {
            for (int f = 0; f < t; ++f)
                extra += B[((size_t)f * NN + t) * DD + hh];             // sum b[f,t][h]
        }

        float4 acc[4];
        #pragma unroll
        for (int r = 0; r < 4; ++r) acc[r] = make_float4(0.f, 0.f, 0.f, 0.f);

        for (int f = 1; f < t; ++f) {
            const float* Wb = W + (((size_t)f * NN + t) * DD + kk * 4) * DD + hg * 4;
            float4 w0 = *reinterpret_cast<const float4*>(Wb + 0 * DD);
            float4 w1 = *reinterpret_cast<const float4*>(Wb + 1 * DD);
            float4 w2 = *reinterpret_cast<const float4*>(Wb + 2 * DD);
            float4 w3 = *reinterpret_cast<const float4*>(Wb + 3 * DD);
            #pragma unroll
            for (int r = 0; r < 4; ++r) {
                float4 rv = *reinterpret_cast<const float4*>(&rowsh[f][r][kk * 4]);
                acc[r].x += rv.x * w0.x + rv.y * w1.x + rv.z * w2.x + rv.w * w3.x;
                acc[r].y += rv.x * w0.y + rv.y * w1.y + rv.z * w2.y + rv.w * w3.y;
                acc[r].z += rv.x * w0.z + rv.y * w1.z + rv.z * w2.z + rv.w * w3.z;
                acc[r].w += rv.x * w0.w + rv.y * w1.w + rv.z * w2.w + rv.w * w3.w;
            }
        }
        #pragma unroll
        for (int r = 0; r < 4; ++r)
            *reinterpret_cast<float4*>(&red[kk][r][hg * 4]) = acc[r];
        __syncthreads();

        // k-reduction: thread (rr, hh)
        float s = extra;
        #pragma unroll
        for (int k2 = 0; k2 < 16; ++k2) s += red[k2][rr][hh];
        rowsh[t][rr][hh] = s;
        if (t == 9) {
            if (!bias)            g_M9[d0 + rr][hh] = s;
            else if (rr == 0)     g_dv9[hh] = s;
        }
        __syncthreads();
    }
}

// ---------------------------------------------------------------------------
// Kernel 2: out = x @ M_9 + d_9.
// 256 blocks x 256 threads, 256 rows/block; x staged transposed in shared,
// M staged with a 4-float mid-row pad (row stride 68) so the 8x16B B-fragment
// chunks hit all 8 bank-groups -> conflict-free LDS.128.
// 8x8 register tile per thread; launch_bounds(256,2) keeps 2 blocks/SM.
// ---------------------------------------------------------------------------
#define MS_STRIDE 68

__global__ __launch_bounds__(256, 2) void gemm_kernel(const float* __restrict__ x,
                                                      float* __restrict__ out) {
    extern __shared__ float sh[];
    float* xT  = sh;                        // [64][256]
    float* Ms  = sh + 64 * 256;             // [64][68] padded/swizzled
    float* dvs = Ms + 64 * MS_STRIDE;       // [64]
    const int tid = threadIdx.x;
    const int R0  = blockIdx.x * 256;

    // stage x rows transposed: thread tid owns global row R0+tid
    const float4* xrow = reinterpret_cast<const float4*>(x + (size_t)(R0 + tid) * DD);
    #pragma unroll
    for (int i = 0; i < 16; ++i) {
        float4 v = xrow[i];
        xT[(4 * i + 0) * 256 + tid] = v.x;
        xT[(4 * i + 1) * 256 + tid] = v.y;
        xT[(4 * i + 2) * 256 + tid] = v.z;
        xT[(4 * i + 3) * 256 + tid] = v.w;
    }
    // stage M_9 with mid-row pad: column c -> c + (c>=32 ? 4 : 0)
    const float* Mflat = &g_M9[0][0];
    #pragma unroll
    for (int i = 0; i < 16; ++i) {
        int idx = i * 256 + tid;            // coalesced
        int d   = idx >> 6;
        int c   = idx & 63;
        Ms[d * MS_STRIDE + c + ((c >= 32) ? 4 : 0)] = Mflat[idx];
    }
    if (tid < 64) dvs[tid] = g_dv9[tid];
    __syncthreads();

    const int rg = tid >> 3;  // 0..31 -> rows rg*8..rg*8+7
    const int cg = tid & 7;   // 0..7  -> cols cg*8..cg*8+7
    const int boff = cg * 8 + ((cg >= 4) ? 4 : 0);   // swizzled base of this col-group

    float acc[64];
    #pragma unroll
    for (int i = 0; i < 64; ++i) acc[i] = 0.f;

    #pragma unroll 4
    for (int d = 0; d < 64; ++d) {
        float4 a0 = *reinterpret_cast<const float4*>(&xT[d * 256 + rg * 8]);
        float4 a1 = *reinterpret_cast<const float4*>(&xT[d * 256 + rg * 8 + 4]);
        float4 b0 = *reinterpret_cast<const float4*>(&Ms[d * MS_STRIDE + boff]);
        float4 b1 = *reinterpret_cast<const float4*>(&Ms[d * MS_STRIDE + boff + 4]);
        float xa[8] = {a0.x, a0.y, a0.z, a0.w, a1.x, a1.y, a1.z, a1.w};
        float mb[8] = {b0.x, b0.y, b0.z, b0.w, b1.x, b1.y, b1.z, b1.w};
        #pragma unroll
        for (int i = 0; i < 8; ++i)
            #pragma unroll
            for (int j = 0; j < 8; ++j)
                acc[i * 8 + j] += xa[i] * mb[j];
    }

    float dvr[8];
    #pragma unroll
    for (int j = 0; j < 8; ++j) dvr[j] = dvs[cg * 8 + j];

    #pragma unroll
    for (int i = 0; i < 8; ++i) {
        const int row = R0 + rg * 8 + i;
        float4 o0 = make_float4(acc[i * 8 + 0] + dvr[0], acc[i * 8 + 1] + dvr[1],
                                acc[i * 8 + 2] + dvr[2], acc[i * 8 + 3] + dvr[3]);
        float4 o1 = make_float4(acc[i * 8 + 4] + dvr[4], acc[i * 8 + 5] + dvr[5],
                                acc[i * 8 + 6] + dvr[6], acc[i * 8 + 7] + dvr[7]);
        float4* orow = reinterpret_cast<float4*>(out + (size_t)row * DD);
        orow[cg * 2 + 0] = o0;
        orow[cg * 2 + 1] = o1;
    }
}

extern "C" void kernel_launch(void* const* d_in, const int* in_sizes, int n_in,
                              void* d_out, int out_size) {
    const float* x = (const float*)d_in[0];
    const float* W = (const float*)d_in[1];
    const float* b = (const float*)d_in[2];
    float* out = (float*)d_out;

    const int smem_bytes = (64 * 256 + 64 * MS_STRIDE + 64) * sizeof(float);  // 83200
    cudaFuncSetAttribute(gemm_kernel, cudaFuncAttributeMaxDynamicSharedMemorySize, smem_bytes);

    precompute_kernel<<<17, 256>>>(W, b);
    gemm_kernel<<<256, 256, smem_bytes>>>(x, out);
}

// round 4
// speedup vs baseline: 1.6512x; 1.0968x over previous
#include <cuda_runtime.h>
#include <cuda_bf16.h>

#define NN 10
#define DD 64

__device__ float g_M9[DD][DD];   // out = x @ g_M9 + g_dv9
__device__ float g_dv9[DD];

// ---------------------------------------------------------------------------
// Kernel 1: collapse the DAG into (M_9, d_9). No grid sync.
// 33 blocks x 256 threads. Blocks 0..31 carry rows {2bi, 2bi+1} of every M_t
// through the chain in shared memory:
//   M_t[d,:] = W[0,t][d,:] + sum_{f=1}^{t-1} M_f[d,:] @ W[f,t]
// Block 32 carries the bias chain d_t (row 0 active, row 1 dummy-zero):
//   d_t = sum_{f<t} b[f,t] + sum_{f=1}^{t-1} d_f @ W[f,t]
// Compute threads: kk = tid>>4 owns k = 4kk..4kk+3, hg = tid&15 owns
// h = 4hg..4hg+3; W read via LDG.128. k-reduction through shared by the
// first 128 threads (rr = tid>>6 in {0,1}, hh = tid&63).
// ---------------------------------------------------------------------------
__global__ __launch_bounds__(256) void precompute_kernel(const float* __restrict__ W,
                                                         const float* __restrict__ B) {
    __shared__ __align__(16) float rowsh[NN][2][DD];  // rowsh[f][r][h]
    __shared__ __align__(16) float red[16][2][DD];    // red[kk][r][h]
    const int tid  = threadIdx.x;
    const int bi   = blockIdx.x;
    const bool bias = (bi == 32);
    const int d0   = bi * 2;
    const int kk   = tid >> 4;    // 0..15
    const int hg   = tid & 15;    // 0..15
    const int rr   = tid >> 6;    // 0..1 (valid for tid < 128)
    const int hh   = tid & 63;

    if (tid < 128)
        rowsh[0][rr][hh] = (!bias && (d0 + rr == hh)) ? 1.f : 0.f;
    __syncthreads();

    for (int t = 1; t <= 9; ++t) {
        // extra term for the reduction phase (f = 0 / biases)
        float extra = 0.f;
        if (tid < 128) {
            if (!bias) {
                extra = W[((size_t)t * DD + (d0 + rr)) * DD + hh];      // W[0,t][d,h]
            } else if (rr == 0) {
                for (int f = 0; f < t; ++f)
                    extra += B[((size_t)f * NN + t) * DD + hh];         // sum_f b[f,t][h]
            }
        }

        float4 acc[2];
        acc[0] = make_float4(0.f, 0.f, 0.f, 0.f);
        acc[1] = make_float4(0.f, 0.f, 0.f, 0.f);

        for (int f = 1; f < t; ++f) {
            const float* Wb = W + (((size_t)f * NN + t) * DD + kk * 4) * DD + hg * 4;
            float4 w0 = *reinterpret_cast<const float4*>(Wb + 0 * DD);
            float4 w1 = *reinterpret_cast<const float4*>(Wb + 1 * DD);
            float4 w2 = *reinterpret_cast<const float4*>(Wb + 2 * DD);
            float4 w3 = *reinterpret_cast<const float4*>(Wb + 3 * DD);
            #pragma unroll
            for (int r = 0; r < 2; ++r) {
                float4 rv = *reinterpret_cast<const float4*>(&rowsh[f][r][kk * 4]);
                acc[r].x += rv.x * w0.x + rv.y * w1.x + rv.z * w2.x + rv.w * w3.x;
                acc[r].y += rv.x * w0.y + rv.y * w1.y + rv.z * w2.y + rv.w * w3.y;
                acc[r].z += rv.x * w0.z + rv.y * w1.z + rv.z * w2.z + rv.w * w3.z;
                acc[r].w += rv.x * w0.w + rv.y * w1.w + rv.z * w2.w + rv.w * w3.w;
            }
        }
        #pragma unroll
        for (int r = 0; r < 2; ++r)
            *reinterpret_cast<float4*>(&red[kk][r][hg * 4]) = acc[r];
        __syncthreads();

        if (tid < 128) {
            float s = extra;
            #pragma unroll
            for (int k2 = 0; k2 < 16; ++k2) s += red[k2][rr][hh];
            rowsh[t][rr][hh] = s;
            if (t == 9) {
                if (!bias)        g_M9[d0 + rr][hh] = s;
                else if (rr == 0) g_dv9[hh] = s;
            }
        }
        __syncthreads();
    }
}

// ---------------------------------------------------------------------------
// Kernel 2: out = x @ M_9 + d_9, packed-FP32 (fma.rn.f32x2 -> FFMA2).
// 256 blocks x 256 threads, 256 rows/block. x staged transposed in shared,
// M staged with mid-row pad (stride 68, conflict-free LDS.128).
// Per thread: 8 rows x 8 cols tile held as 8x4 f32x2 pairs -> 32 FFMA2 per
// k-step instead of 64 scalar FFMA (scalar FFMA is half-rate on sm_103a).
// ---------------------------------------------------------------------------
#define MS_STRIDE 68

__device__ __forceinline__ unsigned long long ffma2(unsigned long long a,
                                                    unsigned long long b,
                                                    unsigned long long c) {
    unsigned long long d;
    asm("fma.rn.f32x2 %0, %1, %2, %3;" : "=l"(d) : "l"(a), "l"(b), "l"(c));
    return d;
}
__device__ __forceinline__ unsigned long long fadd2(unsigned long long a,
                                                    unsigned long long b) {
    unsigned long long d;
    asm("add.rn.f32x2 %0, %1, %2;" : "=l"(d) : "l"(a), "l"(b));
    return d;
}
__device__ __forceinline__ unsigned long long fdup(float v) {
    unsigned long long d;
    asm("mov.b64 %0, {%1, %1};" : "=l"(d) : "f"(v));
    return d;
}

__global__ __launch_bounds__(256, 2) void gemm_kernel(const float* __restrict__ x,
                                                      float* __restrict__ out) {
    extern __shared__ float sh[];
    float* xT  = sh;                        // [64][256]
    float* Ms  = sh + 64 * 256;             // [64][68] padded
    float* dvs = Ms + 64 * MS_STRIDE;       // [64]
    const int tid = threadIdx.x;
    const int R0  = blockIdx.x * 256;

    // stage x rows transposed: thread tid owns global row R0+tid
    const float4* xrow = reinterpret_cast<const float4*>(x + (size_t)(R0 + tid) * DD);
    #pragma unroll
    for (int i = 0; i < 16; ++i) {
        float4 v = xrow[i];
        xT[(4 * i + 0) * 256 + tid] = v.x;
        xT[(4 * i + 1) * 256 + tid] = v.y;
        xT[(4 * i + 2) * 256 + tid] = v.z;
        xT[(4 * i + 3) * 256 + tid] = v.w;
    }
    // stage M_9 with mid-row pad: column c -> c + (c>=32 ? 4 : 0)
    const float* Mflat = &g_M9[0][0];
    #pragma unroll
    for (int i = 0; i < 16; ++i) {
        int idx = i * 256 + tid;            // coalesced
        int d   = idx >> 6;
        int c   = idx & 63;
        Ms[d * MS_STRIDE + c + ((c >= 32) ? 4 : 0)] = Mflat[idx];
    }
    if (tid < 64) dvs[tid] = g_dv9[tid];
    __syncthreads();

    const int rg = tid >> 3;  // 0..31 -> rows rg*8..rg*8+7
    const int cg = tid & 7;   // 0..7  -> cols cg*8..cg*8+7
    const int boff = cg * 8 + ((cg >= 4) ? 4 : 0);   // padded base of col-group

    unsigned long long acc2[32];            // [8 rows][4 col-pairs]
    #pragma unroll
    for (int i = 0; i < 32; ++i) acc2[i] = 0ull;

    #pragma unroll 4
    for (int d = 0; d < 64; ++d) {
        float4 a0 = *reinterpret_cast<const float4*>(&xT[d * 256 + rg * 8]);
        float4 a1 = *reinterpret_cast<const float4*>(&xT[d * 256 + rg * 8 + 4]);
        ulonglong2 bb0 = *reinterpret_cast<const ulonglong2*>(&Ms[d * MS_STRIDE + boff]);
        ulonglong2 bb1 = *reinterpret_cast<const ulonglong2*>(&Ms[d * MS_STRIDE + boff + 4]);
        unsigned long long mb[4] = {bb0.x, bb0.y, bb1.x, bb1.y};
        float xa[8] = {a0.x, a0.y, a0.z, a0.w, a1.x, a1.y, a1.z, a1.w};
        #pragma unroll
        for (int i = 0; i < 8; ++i) {
            unsigned long long xd = fdup(xa[i]);
            #pragma unroll
            for (int j = 0; j < 4; ++j)
                acc2[i * 4 + j] = ffma2(xd, mb[j], acc2[i * 4 + j]);
        }
    }

    unsigned long long dvp[4];
    #pragma unroll
    for (int j = 0; j < 4; ++j)
        dvp[j] = *reinterpret_cast<const unsigned long long*>(&dvs[cg * 8 + 2 * j]);

    #pragma unroll
    for (int i = 0; i < 8; ++i) {
        const int row = R0 + rg * 8 + i;
        ulonglong2 s0, s1;
        s0.x = fadd2(acc2[i * 4 + 0], dvp[0]);
        s0.y = fadd2(acc2[i * 4 + 1], dvp[1]);
        s1.x = fadd2(acc2[i * 4 + 2], dvp[2]);
        s1.y = fadd2(acc2[i * 4 + 3], dvp[3]);
        ulonglong2* orow = reinterpret_cast<ulonglong2*>(out + (size_t)row * DD + cg * 8);
        orow[0] = s0;
        orow[1] = s1;
    }
}

extern "C" void kernel_launch(void* const* d_in, const int* in_sizes, int n_in,
                              void* d_out, int out_size) {
    const float* x = (const float*)d_in[0];
    const float* W = (const float*)d_in[1];
    const float* b = (const float*)d_in[2];
    float* out = (float*)d_out;

    const int smem_bytes = (64 * 256 + 64 * MS_STRIDE + 64) * sizeof(float);  // 83200
    cudaFuncSetAttribute(gemm_kernel, cudaFuncAttributeMaxDynamicSharedMemorySize, smem_bytes);

    precompute_kernel<<<33, 256>>>(W, b);
    gemm_kernel<<<256, 256, smem_bytes>>>(x, out);
}

// round 5
// speedup vs baseline: 2.2512x; 1.3633x over previous
#include <cuda_runtime.h>
#include <cuda_bf16.h>

#define NN 10
#define DD 64

__device__ float g_M9[DD][DD];   // out = x @ g_M9 + g_dv9
__device__ float g_dv9[DD];

// ---------------------------------------------------------------------------
// Kernel 1: collapse the DAG into (M_9, d_9). 33 blocks x 256 threads.
// Blocks 0..31: rows {2bi,2bi+1} of each M_t; block 32: bias chain.
// t-loop FULLY UNROLLED so each step's W loads (up to 32 LDG.128) batch and
// overlap a single L2 round-trip instead of (t-1) serialized ones.
// ---------------------------------------------------------------------------
__global__ __launch_bounds__(256) void precompute_kernel(const float* __restrict__ W,
                                                         const float* __restrict__ B) {
    __shared__ __align__(16) float rowsh[NN][2][DD];
    __shared__ __align__(16) float red[16][2][DD];
    const int tid  = threadIdx.x;
    const int bi   = blockIdx.x;
    const bool bias = (bi == 32);
    const int d0   = bi * 2;
    const int kk   = tid >> 4;    // 0..15: k = 4kk..4kk+3
    const int hg   = tid & 15;    // 0..15: h = 4hg..4hg+3
    const int rr   = tid >> 6;    // 0..1 (tid < 128)
    const int hh   = tid & 63;

    if (tid < 128)
        rowsh[0][rr][hh] = (!bias && (d0 + rr == hh)) ? 1.f : 0.f;
    __syncthreads();

    #pragma unroll
    for (int t = 1; t <= 9; ++t) {
        float extra = 0.f;
        if (tid < 128) {
            if (!bias) {
                extra = W[((size_t)t * DD + (d0 + rr)) * DD + hh];      // W[0,t][d,h]
            } else if (rr == 0) {
                #pragma unroll
                for (int f = 0; f < t; ++f)
                    extra += B[((size_t)f * NN + t) * DD + hh];
            }
        }

        float4 a0 = make_float4(0.f, 0.f, 0.f, 0.f);
        float4 a1 = make_float4(0.f, 0.f, 0.f, 0.f);

        #pragma unroll
        for (int f = 1; f < t; ++f) {
            const float* Wb = W + (((size_t)f * NN + t) * DD + kk * 4) * DD + hg * 4;
            float4 w0 = *reinterpret_cast<const float4*>(Wb + 0 * DD);
            float4 w1 = *reinterpret_cast<const float4*>(Wb + 1 * DD);
            float4 w2 = *reinterpret_cast<const float4*>(Wb + 2 * DD);
            float4 w3 = *reinterpret_cast<const float4*>(Wb + 3 * DD);
            float4 r0 = *reinterpret_cast<const float4*>(&rowsh[f][0][kk * 4]);
            float4 r1 = *reinterpret_cast<const float4*>(&rowsh[f][1][kk * 4]);
            a0.x += r0.x * w0.x + r0.y * w1.x + r0.z * w2.x + r0.w * w3.x;
            a0.y += r0.x * w0.y + r0.y * w1.y + r0.z * w2.y + r0.w * w3.y;
            a0.z += r0.x * w0.z + r0.y * w1.z + r0.z * w2.z + r0.w * w3.z;
            a0.w += r0.x * w0.w + r0.y * w1.w + r0.z * w2.w + r0.w * w3.w;
            a1.x += r1.x * w0.x + r1.y * w1.x + r1.z * w2.x + r1.w * w3.x;
            a1.y += r1.x * w0.y + r1.y * w1.y + r1.z * w2.y + r1.w * w3.y;
            a1.z += r1.x * w0.z + r1.y * w1.z + r1.z * w2.z + r1.w * w3.z;
            a1.w += r1.x * w0.w + r1.y * w1.w + r1.z * w2.w + r1.w * w3.w;
        }
        *reinterpret_cast<float4*>(&red[kk][0][hg * 4]) = a0;
        *reinterpret_cast<float4*>(&red[kk][1][hg * 4]) = a1;
        __syncthreads();

        if (tid < 128) {
            float s = extra;
            #pragma unroll
            for (int k2 = 0; k2 < 16; ++k2) s += red[k2][rr][hh];
            rowsh[t][rr][hh] = s;
            if (t == 9) {
                if (!bias)        g_M9[d0 + rr][hh] = s;
                else if (rr == 0) g_dv9[hh] = s;
            }
        }
        __syncthreads();
    }
}

// ---------------------------------------------------------------------------
// Kernel 2: out = x @ M_9 + d_9 on tensor cores (mma.sync m16n8k8 tf32).
// 256 blocks x 256 threads (8 warps), 256 rows/block.
// k-dimension pairwise-permuted in BOTH operands (phys 2w <-> logical w,
// phys 2w+1 <-> logical w+4) so each A/B fragment pair is one LDS.64;
// stride 72 words makes every fragment load conflict-free (16-lane phases).
// Inputs rna-rounded to tf32 at staging. Bias folded into the epilogue.
// ---------------------------------------------------------------------------
#define XS 72                      // x_s row stride (floats)
#define MS 72                      // M_sT row stride (floats)

__device__ __forceinline__ unsigned tf32_rna(float v) {
    unsigned u = __float_as_uint(v);
    return (u + 0x1000u) & 0xFFFFE000u;
}

__device__ __forceinline__ void mma_tf32(float& c0, float& c1, float& c2, float& c3,
                                         unsigned a0, unsigned a1, unsigned a2, unsigned a3,
                                         unsigned b0, unsigned b1) {
    asm volatile(
        "mma.sync.aligned.m16n8k8.row.col.f32.tf32.tf32.f32 "
        "{%0,%1,%2,%3}, {%4,%5,%6,%7}, {%8,%9}, {%0,%1,%2,%3};"
        : "+f"(c0), "+f"(c1), "+f"(c2), "+f"(c3)
        : "r"(a0), "r"(a1), "r"(a2), "r"(a3), "r"(b0), "r"(b1));
}

__global__ __launch_bounds__(256, 2) void gemm_kernel(const float* __restrict__ x,
                                                      float* __restrict__ out) {
    extern __shared__ __align__(16) unsigned sh[];
    unsigned* xs  = sh;                    // [256][XS] tf32 bits
    unsigned* Ms  = sh + 256 * XS;         // [64][MS]  M transposed: [n][k-permuted]
    float*    dvs = reinterpret_cast<float*>(Ms + 64 * MS);  // [64]
    const int tid = threadIdx.x;
    const int R0  = blockIdx.x * 256;

    // ---- stage x row tid with pairwise k-permute + tf32 rounding ----
    {
        const float4* xrow = reinterpret_cast<const float4*>(x + (size_t)(R0 + tid) * DD);
        #pragma unroll
        for (int k8 = 0; k8 < 8; ++k8) {
            float4 v0 = xrow[2 * k8 + 0];   // logical w = 0..3
            float4 v1 = xrow[2 * k8 + 1];   // logical w = 4..7
            uint4 s0 = make_uint4(tf32_rna(v0.x), tf32_rna(v1.x), tf32_rna(v0.y), tf32_rna(v1.y));
            uint4 s1 = make_uint4(tf32_rna(v0.z), tf32_rna(v1.z), tf32_rna(v0.w), tf32_rna(v1.w));
            *reinterpret_cast<uint4*>(&xs[tid * XS + 8 * k8 + 0]) = s0;
            *reinterpret_cast<uint4*>(&xs[tid * XS + 8 * k8 + 4]) = s1;
        }
    }
    // ---- stage M transposed [n][k] with same k-permute + tf32 rounding ----
    {
        const float* Mflat = &g_M9[0][0];
        #pragma unroll
        for (int i = 0; i < 16; ++i) {
            int idx = i * 256 + tid;        // coalesced read
            int k = idx >> 6, n = idx & 63;
            int w = k & 7;
            int kp = (k & ~7) | ((w < 4) ? (2 * w) : (2 * (w - 4) + 1));
            Ms[n * MS + kp] = tf32_rna(Mflat[idx]);
        }
    }
    if (tid < 64) dvs[tid] = g_dv9[tid];
    __syncthreads();

    const int w    = tid >> 5;        // warp 0..7: rows w*32 .. w*32+31
    const int lane = tid & 31;
    const int g    = lane >> 2;       // group 0..7
    const int t    = lane & 3;        // thread-in-group

    // bias pairs per n-tile: cols 8n + 2t, 8n + 2t + 1
    float2 dvp[8];
    #pragma unroll
    for (int n = 0; n < 8; ++n)
        dvp[n] = *reinterpret_cast<const float2*>(&dvs[8 * n + 2 * t]);

    float acc[2][8][4];
    #pragma unroll
    for (int rt = 0; rt < 2; ++rt)
        #pragma unroll
        for (int n = 0; n < 8; ++n)
            #pragma unroll
            for (int c = 0; c < 4; ++c) acc[rt][n][c] = 0.f;

    const int rbase = w * 32;

    #pragma unroll
    for (int k8 = 0; k8 < 8; ++k8) {
        const int kcol = 8 * k8 + 2 * t;
        // B fragments: one LDS.64 per n-tile (conflict-free)
        uint2 bf[8];
        #pragma unroll
        for (int n = 0; n < 8; ++n)
            bf[n] = *reinterpret_cast<const uint2*>(&Ms[(8 * n + g) * MS + kcol]);
        // A fragments: 2 row-tiles x 2 LDS.64
        uint2 aA0 = *reinterpret_cast<const uint2*>(&xs[(rbase + g)      * XS + kcol]);
        uint2 aA1 = *reinterpret_cast<const uint2*>(&xs[(rbase + 8 + g)  * XS + kcol]);
        uint2 aB0 = *reinterpret_cast<const uint2*>(&xs[(rbase + 16 + g) * XS + kcol]);
        uint2 aB1 = *reinterpret_cast<const uint2*>(&xs[(rbase + 24 + g) * XS + kcol]);
        #pragma unroll
        for (int n = 0; n < 8; ++n) {
            mma_tf32(acc[0][n][0], acc[0][n][1], acc[0][n][2], acc[0][n][3],
                     aA0.x, aA1.x, aA0.y, aA1.y, bf[n].x, bf[n].y);
            mma_tf32(acc[1][n][0], acc[1][n][1], acc[1][n][2], acc[1][n][3],
                     aB0.x, aB1.x, aB0.y, aB1.y, bf[n].x, bf[n].y);
        }
    }

    // ---- epilogue: add bias, STG.64 (sector-complete across the 4 t-lanes) ----
    #pragma unroll
    for (int rt = 0; rt < 2; ++rt) {
        const int row0 = R0 + rbase + rt * 16 + g;
        #pragma unroll
        for (int n = 0; n < 8; ++n) {
            float2 o0 = make_float2(acc[rt][n][0] + dvp[n].x, acc[rt][n][1] + dvp[n].y);
            float2 o1 = make_float2(acc[rt][n][2] + dvp[n].x, acc[rt][n][3] + dvp[n].y);
            *reinterpret_cast<float2*>(out + (size_t)row0 * DD + 8 * n + 2 * t)       = o0;
            *reinterpret_cast<float2*>(out + (size_t)(row0 + 8) * DD + 8 * n + 2 * t) = o1;
        }
    }
}

extern "C" void kernel_launch(void* const* d_in, const int* in_sizes, int n_in,
                              void* d_out, int out_size) {
    const float* x = (const float*)d_in[0];
    const float* W = (const float*)d_in[1];
    const float* b = (const float*)d_in[2];
    float* out = (float*)d_out;

    const int smem_bytes = (256 * XS + 64 * MS) * 4 + 64 * 4;   // 92416
    cudaFuncSetAttribute(gemm_kernel, cudaFuncAttributeMaxDynamicSharedMemorySize, smem_bytes);

    precompute_kernel<<<33, 256>>>(W, b);
    gemm_kernel<<<256, 256, smem_bytes>>>(x, out);
}

// round 7
// speedup vs baseline: 2.3644x; 1.0503x over previous
#include <cuda_runtime.h>
#include <cuda_bf16.h>

#define NN 10
#define DD 64

__device__ float g_M9[DD][DD];   // out = x @ g_M9 + g_dv9
__device__ float g_dv9[DD];

// ---------------------------------------------------------------------------
// Kernel 1: collapse the DAG into (M_9, d_9). 33 blocks x 512 threads.
// Blocks 0..31: rows {2bi,2bi+1} of each M_t; block 32: bias chain.
// 32-way k-split (kk owns k = 2kk..2kk+1), 16-way h-split.
// Fires PDL trigger at entry so the GEMM kernel can start loading x.
// ---------------------------------------------------------------------------
__global__ __launch_bounds__(512) void precompute_kernel(const float* __restrict__ W,
                                                         const float* __restrict__ B) {
    asm volatile("griddepcontrol.launch_dependents;");

    __shared__ __align__(16) float rowsh[NN][2][DD];
    __shared__ __align__(16) float red[32][2][DD];
    const int tid  = threadIdx.x;
    const int bi   = blockIdx.x;
    const bool bias = (bi == 32);
    const int d0   = bi * 2;
    const int kk   = tid >> 4;    // 0..31: k = 2kk..2kk+1
    const int hg   = tid & 15;    // 0..15: h = 4hg..4hg+3
    const int rr   = tid >> 6;    // 0..1 (tid < 128)
    const int hh   = tid & 63;

    if (tid < 128)
        rowsh[0][rr][hh] = (!bias && (d0 + rr == hh)) ? 1.f : 0.f;
    __syncthreads();

    #pragma unroll
    for (int t = 1; t <= 9; ++t) {
        float extra = 0.f;
        if (tid < 128) {
            if (!bias) {
                extra = W[((size_t)t * DD + (d0 + rr)) * DD + hh];      // W[0,t][d,h]
            } else if (rr == 0) {
                #pragma unroll
                for (int f = 0; f < t; ++f)
                    extra += B[((size_t)f * NN + t) * DD + hh];
            }
        }

        float4 a0 = make_float4(0.f, 0.f, 0.f, 0.f);
        float4 a1 = make_float4(0.f, 0.f, 0.f, 0.f);

        #pragma unroll
        for (int f = 1; f < t; ++f) {
            const float* Wb = W + (((size_t)f * NN + t) * DD + kk * 2) * DD + hg * 4;
            float4 w0 = *reinterpret_cast<const float4*>(Wb + 0 * DD);
            float4 w1 = *reinterpret_cast<const float4*>(Wb + 1 * DD);
            float r0k0 = rowsh[f][0][2 * kk], r0k1 = rowsh[f][0][2 * kk + 1];
            float r1k0 = rowsh[f][1][2 * kk], r1k1 = rowsh[f][1][2 * kk + 1];
            a0.x += r0k0 * w0.x + r0k1 * w1.x;
            a0.y += r0k0 * w0.y + r0k1 * w1.y;
            a0.z += r0k0 * w0.z + r0k1 * w1.z;
            a0.w += r0k0 * w0.w + r0k1 * w1.w;
            a1.x += r1k0 * w0.x + r1k1 * w1.x;
            a1.y += r1k0 * w0.y + r1k1 * w1.y;
            a1.z += r1k0 * w0.z + r1k1 * w1.z;
            a1.w += r1k0 * w0.w + r1k1 * w1.w;
        }
        *reinterpret_cast<float4*>(&red[kk][0][hg * 4]) = a0;
        *reinterpret_cast<float4*>(&red[kk][1][hg * 4]) = a1;
        __syncthreads();

        if (tid < 128) {
            float s = extra;
            #pragma unroll
            for (int k2 = 0; k2 < 32; ++k2) s += red[k2][rr][hh];
            rowsh[t][rr][hh] = s;
            if (t == 9) {
                if (!bias)        g_M9[d0 + rr][hh] = s;
                else if (rr == 0) g_dv9[hh] = s;
            }
        }
        __syncthreads();
    }
}

// ---------------------------------------------------------------------------
// Kernel 2: out = x @ M_9 + d_9 (mma.sync m16n8k8 tf32).
// 512 blocks x 256 threads (8 warps), 128 rows/block, 16 rows/warp.
// A fragments loaded DIRECTLY from global x (LDG.64, sector-perfect) and
// tf32-rounded into registers BEFORE griddepcontrol.wait -> the entire x
// read overlaps the precompute kernel (PDL). B = M_9^T in smem, stride 72.
// k-slot convention: slot pair (t, t+4) <-> physical columns (2t, 2t+1),
// applied identically to A and B, so no permutation is needed anywhere.
// ---------------------------------------------------------------------------
#define MS 72

__device__ __forceinline__ unsigned tf32_rna(float v) {
    unsigned u = __float_as_uint(v);
    return (u + 0x1000u) & 0xFFFFE000u;
}

__device__ __forceinline__ void mma_tf32(float& c0, float& c1, float& c2, float& c3,
                                         unsigned a0, unsigned a1, unsigned a2, unsigned a3,
                                         unsigned b0, unsigned b1) {
    asm volatile(
        "mma.sync.aligned.m16n8k8.row.col.f32.tf32.tf32.f32 "
        "{%0,%1,%2,%3}, {%4,%5,%6,%7}, {%8,%9}, {%0,%1,%2,%3};"
        : "+f"(c0), "+f"(c1), "+f"(c2), "+f"(c3)
        : "r"(a0), "r"(a1), "r"(a2), "r"(a3), "r"(b0), "r"(b1));
}

__global__ __launch_bounds__(256, 2) void gemm_kernel(const float* __restrict__ x,
                                                      float* __restrict__ out) {
    extern __shared__ __align__(16) unsigned sh[];
    unsigned* Ms  = sh;                                   // [64][MS]: Ms[n][k] = M[k][n]
    float*    dvs = reinterpret_cast<float*>(Ms + 64 * MS);
    const int tid  = threadIdx.x;
    const int w    = tid >> 5;
    const int lane = tid & 31;
    const int g    = lane >> 2;
    const int t    = lane & 3;
    const int row0 = blockIdx.x * 128 + w * 16 + g;       // rows row0, row0+8

    // ---- pre-wait: pull this thread's entire A operand from global ----
    unsigned af[8][4];                                    // [k8][slot]
    {
        const float2* xr0 = reinterpret_cast<const float2*>(x + (size_t)row0 * DD);
        const float2* xr1 = reinterpret_cast<const float2*>(x + (size_t)(row0 + 8) * DD);
        #pragma unroll
        for (int k8 = 0; k8 < 8; ++k8) {
            float2 v0 = xr0[4 * k8 + t];                  // row g,   cols 8k8+2t, +1
            float2 v1 = xr1[4 * k8 + t];                  // row g+8
            af[k8][0] = tf32_rna(v0.x);                   // slot t    (phys 2t)
            af[k8][2] = tf32_rna(v0.y);                   // slot t+4  (phys 2t+1)
            af[k8][1] = tf32_rna(v1.x);
            af[k8][3] = tf32_rna(v1.y);
        }
    }

    // ---- wait for precompute results, then stage M ----
    asm volatile("griddepcontrol.wait;" ::: "memory");
    {
        const float* Mflat = &g_M9[0][0];
        #pragma unroll
        for (int i = 0; i < 16; ++i) {
            int idx = i * 256 + tid;                      // coalesced read
            int k = idx >> 6, n = idx & 63;
            Ms[n * MS + k] = tf32_rna(Mflat[idx]);
        }
        if (tid < 64) dvs[tid] = g_dv9[tid];
    }
    __syncthreads();

    float acc[8][4];
    #pragma unroll
    for (int n = 0; n < 8; ++n)
        #pragma unroll
        for (int c = 0; c < 4; ++c) acc[n][c] = 0.f;

    #pragma unroll
    for (int k8 = 0; k8 < 8; ++k8) {
        const int kcol = 8 * k8 + 2 * t;
        #pragma unroll
        for (int n = 0; n < 8; ++n) {
            uint2 bf = *reinterpret_cast<const uint2*>(&Ms[(8 * n + g) * MS + kcol]);
            mma_tf32(acc[n][0], acc[n][1], acc[n][2], acc[n][3],
                     af[k8][0], af[k8][1], af[k8][2], af[k8][3], bf.x, bf.y);
        }
    }

    // ---- epilogue: bias + STG.64 (4 t-lanes complete each 32B sector) ----
    #pragma unroll
    for (int n = 0; n < 8; ++n) {
        float2 dv = *reinterpret_cast<const float2*>(&dvs[8 * n + 2 * t]);
        float2 o0 = make_float2(acc[n][0] + dv.x, acc[n][1] + dv.y);
        float2 o1 = make_float2(acc[n][2] + dv.x, acc[n][3] + dv.y);
        *reinterpret_cast<float2*>(out + (size_t)row0 * DD + 8 * n + 2 * t)       = o0;
        *reinterpret_cast<float2*>(out + (size_t)(row0 + 8) * DD + 8 * n + 2 * t) = o1;
    }
}

extern "C" void kernel_launch(void* const* d_in, const int* in_sizes, int n_in,
                              void* d_out, int out_size) {
    const float* x = (const float*)d_in[0];
    const float* W = (const float*)d_in[1];
    const float* b = (const float*)d_in[2];
    float* out = (float*)d_out;

    const int smem_bytes = (64 * MS) * 4 + 64 * 4;        // 18688
    cudaFuncSetAttribute(gemm_kernel, cudaFuncAttributeMaxDynamicSharedMemorySize, smem_bytes);

    precompute_kernel<<<33, 512>>>(W, b);

    cudaLaunchConfig_t cfg = {};
    cfg.gridDim        = dim3(512);
    cfg.blockDim       = dim3(256);
    cfg.dynamicSmemBytes = smem_bytes;
    cfg.stream         = 0;
    cudaLaunchAttribute attr[1];
    attr[0].id = cudaLaunchAttributeProgrammaticStreamSerialization;
    attr[0].val.programmaticStreamSerializationAllowed = 1;
    cfg.attrs    = attr;
    cfg.numAttrs = 1;
    cudaLaunchKernelEx(&cfg, gemm_kernel, x, out);
}

// round 8
// speedup vs baseline: 2.6764x; 1.1319x over previous
#include <cuda_runtime.h>
#include <cuda_bf16.h>

#define NN 10
#define DD 64
#define MS 72

__device__ float g_M9[DD][DD];            // out = x @ g_M9 + g_dv9
__device__ float g_dv9[DD];
__device__ volatile unsigned g_flag;      // precompute-done counter (0..33)
__device__ unsigned g_done;               // gemm-block completion counter

// ---------------------------------------------------------------------------
// Round 8 theory (see commit msg): FUSE the two kernels into one 289-block
// grid (33 precompute-role + 256 gemm-role blocks, all co-resident in one
// wave at 2 blocks/SM -> spin-wait is deadlock-free). Gemm blocks prefetch
// their ENTIRE x operand (32 LDG.64/thread, <55/warp cap) while the
// precompute chain runs, spin on a one-shot flag, then do 128 mma + stores.
// This removes the inter-kernel gap AND truly overlaps the 16.8 MB x read
// with the serial DAG-collapse chain.
// ---------------------------------------------------------------------------

__device__ __forceinline__ unsigned tf32_rna(float v) {
    unsigned u = __float_as_uint(v);
    return (u + 0x1000u) & 0xFFFFE000u;
}

__device__ __forceinline__ void mma_tf32(float& c0, float& c1, float& c2, float& c3,
                                         unsigned a0, unsigned a1, unsigned a2, unsigned a3,
                                         unsigned b0, unsigned b1) {
    asm volatile(
        "mma.sync.aligned.m16n8k8.row.col.f32.tf32.tf32.f32 "
        "{%0,%1,%2,%3}, {%4,%5,%6,%7}, {%8,%9}, {%0,%1,%2,%3};"
        : "+f"(c0), "+f"(c1), "+f"(c2), "+f"(c3)
        : "r"(a0), "r"(a1), "r"(a2), "r"(a3), "r"(b0), "r"(b1));
}

// ---- precompute role: blocks 0..32, 256 threads -----------------------------
__device__ void precompute_role(const float* __restrict__ W,
                                const float* __restrict__ B,
                                float* sh, int bi) {
    float* rowsh = sh;                    // [NN][2][DD]  = 1280 floats
    float* red   = sh + NN * 2 * DD;      // [16][2][DD]  = 2048 floats
    const int tid  = threadIdx.x;
    const bool bias = (bi == 32);
    const int d0   = bi * 2;
    const int kk   = tid >> 4;    // 0..15: k = 4kk..4kk+3
    const int hg   = tid & 15;    // 0..15: h = 4hg..4hg+3
    const int rr   = tid >> 6;    // 0..1 (tid < 128)
    const int hh   = tid & 63;

    if (tid < 128)
        rowsh[(0 * 2 + rr) * DD + hh] = (!bias && (d0 + rr == hh)) ? 1.f : 0.f;
    __syncthreads();

    #pragma unroll
    for (int t = 1; t <= 9; ++t) {
        float extra = 0.f;
        if (tid < 128) {
            if (!bias) {
                extra = W[((size_t)t * DD + (d0 + rr)) * DD + hh];      // W[0,t][d,h]
            } else if (rr == 0) {
                #pragma unroll
                for (int f = 0; f < t; ++f)
                    extra += B[((size_t)f * NN + t) * DD + hh];
            }
        }

        float4 a0 = make_float4(0.f, 0.f, 0.f, 0.f);
        float4 a1 = make_float4(0.f, 0.f, 0.f, 0.f);

        #pragma unroll
        for (int f = 1; f < t; ++f) {
            const float* Wb = W + (((size_t)f * NN + t) * DD + kk * 4) * DD + hg * 4;
            float4 w0 = *reinterpret_cast<const float4*>(Wb + 0 * DD);
            float4 w1 = *reinterpret_cast<const float4*>(Wb + 1 * DD);
            float4 w2 = *reinterpret_cast<const float4*>(Wb + 2 * DD);
            float4 w3 = *reinterpret_cast<const float4*>(Wb + 3 * DD);
            float4 r0 = *reinterpret_cast<const float4*>(&rowsh[(f * 2 + 0) * DD + kk * 4]);
            float4 r1 = *reinterpret_cast<const float4*>(&rowsh[(f * 2 + 1) * DD + kk * 4]);
            a0.x += r0.x * w0.x + r0.y * w1.x + r0.z * w2.x + r0.w * w3.x;
            a0.y += r0.x * w0.y + r0.y * w1.y + r0.z * w2.y + r0.w * w3.y;
            a0.z += r0.x * w0.z + r0.y * w1.z + r0.z * w2.z + r0.w * w3.z;
            a0.w += r0.x * w0.w + r0.y * w1.w + r0.z * w2.w + r0.w * w3.w;
            a1.x += r1.x * w0.x + r1.y * w1.x + r1.z * w2.x + r1.w * w3.x;
            a1.y += r1.x * w0.y + r1.y * w1.y + r1.z * w2.y + r1.w * w3.y;
            a1.z += r1.x * w0.z + r1.y * w1.z + r1.z * w2.z + r1.w * w3.z;
            a1.w += r1.x * w0.w + r1.y * w1.w + r1.z * w2.w + r1.w * w3.w;
        }
        *reinterpret_cast<float4*>(&red[(kk * 2 + 0) * DD + hg * 4]) = a0;
        *reinterpret_cast<float4*>(&red[(kk * 2 + 1) * DD + hg * 4]) = a1;
        __syncthreads();

        if (tid < 128) {
            float s = extra;
            #pragma unroll
            for (int k2 = 0; k2 < 16; ++k2) s += red[(k2 * 2 + rr) * DD + hh];
            rowsh[(t * 2 + rr) * DD + hh] = s;
            if (t == 9) {
                if (!bias)        g_M9[d0 + rr][hh] = s;
                else if (rr == 0) g_dv9[hh] = s;
            }
        }
        __syncthreads();
    }

    // publish: release results, then arrive on the flag
    __threadfence();
    __syncthreads();
    if (tid == 0) atomicAdd((unsigned*)&g_flag, 1u);
}

// ---- gemm role: blocks 33..288, 256 rows each -------------------------------
__device__ void gemm_role(const float* __restrict__ x, float* __restrict__ out,
                          unsigned* shb, int bid) {
    unsigned* Msm = shb;                                  // [64][MS]: Ms[n][k] = M[k][n]
    float*    dvs = reinterpret_cast<float*>(shb + 64 * MS);
    const int tid  = threadIdx.x;
    const int w    = tid >> 5;
    const int lane = tid & 31;
    const int g    = lane >> 2;
    const int t    = lane & 3;
    const int R0   = bid * 256;
    const int rowA = R0 + w * 16 + g;                     // half-1 rows: rowA, rowA+8
    const int rowB = rowA + 128;                          // half-2 rows

    // ---- prefetch BOTH halves of A from global (overlaps precompute) ----
    unsigned af1[8][4], af2[8][4];
    {
        const float2* a0 = reinterpret_cast<const float2*>(x + (size_t)rowA * DD);
        const float2* a1 = reinterpret_cast<const float2*>(x + (size_t)(rowA + 8) * DD);
        const float2* b0 = reinterpret_cast<const float2*>(x + (size_t)rowB * DD);
        const float2* b1 = reinterpret_cast<const float2*>(x + (size_t)(rowB + 8) * DD);
        #pragma unroll
        for (int k8 = 0; k8 < 8; ++k8) {
            float2 v0 = a0[4 * k8 + t];
            float2 v1 = a1[4 * k8 + t];
            float2 u0 = b0[4 * k8 + t];
            float2 u1 = b1[4 * k8 + t];
            af1[k8][0] = tf32_rna(v0.x); af1[k8][2] = tf32_rna(v0.y);
            af1[k8][1] = tf32_rna(v1.x); af1[k8][3] = tf32_rna(v1.y);
            af2[k8][0] = tf32_rna(u0.x); af2[k8][2] = tf32_rna(u0.y);
            af2[k8][1] = tf32_rna(u1.x); af2[k8][3] = tf32_rna(u1.y);
        }
    }

    // ---- wait for the DAG collapse to finish ----
    while (g_flag < 33u) __nanosleep(64);
    __threadfence();

    // ---- stage M^T + bias in shared ----
    {
        const float* Mflat = &g_M9[0][0];
        #pragma unroll
        for (int i = 0; i < 16; ++i) {
            int idx = i * 256 + tid;                      // coalesced
            int k = idx >> 6, n = idx & 63;
            Msm[n * MS + k] = tf32_rna(Mflat[idx]);
        }
        if (tid < 64) dvs[tid] = g_dv9[tid];
    }
    __syncthreads();

    float2 dvp[8];
    #pragma unroll
    for (int n = 0; n < 8; ++n)
        dvp[n] = *reinterpret_cast<const float2*>(&dvs[8 * n + 2 * t]);

    // ---- half 1 ----
    {
        float acc[8][4];
        #pragma unroll
        for (int n = 0; n < 8; ++n)
            #pragma unroll
            for (int c = 0; c < 4; ++c) acc[n][c] = 0.f;
        #pragma unroll
        for (int k8 = 0; k8 < 8; ++k8) {
            const int kcol = 8 * k8 + 2 * t;
            #pragma unroll
            for (int n = 0; n < 8; ++n) {
                uint2 bf = *reinterpret_cast<const uint2*>(&Msm[(8 * n + g) * MS + kcol]);
                mma_tf32(acc[n][0], acc[n][1], acc[n][2], acc[n][3],
                         af1[k8][0], af1[k8][1], af1[k8][2], af1[k8][3], bf.x, bf.y);
            }
        }
        #pragma unroll
        for (int n = 0; n < 8; ++n) {
            float2 o0 = make_float2(acc[n][0] + dvp[n].x, acc[n][1] + dvp[n].y);
            float2 o1 = make_float2(acc[n][2] + dvp[n].x, acc[n][3] + dvp[n].y);
            *reinterpret_cast<float2*>(out + (size_t)rowA * DD + 8 * n + 2 * t)       = o0;
            *reinterpret_cast<float2*>(out + (size_t)(rowA + 8) * DD + 8 * n + 2 * t) = o1;
        }
    }
    // ---- half 2 ----
    {
        float acc[8][4];
        #pragma unroll
        for (int n = 0; n < 8; ++n)
            #pragma unroll
            for (int c = 0; c < 4; ++c) acc[n][c] = 0.f;
        #pragma unroll
        for (int k8 = 0; k8 < 8; ++k8) {
            const int kcol = 8 * k8 + 2 * t;
            #pragma unroll
            for (int n = 0; n < 8; ++n) {
                uint2 bf = *reinterpret_cast<const uint2*>(&Msm[(8 * n + g) * MS + kcol]);
                mma_tf32(acc[n][0], acc[n][1], acc[n][2], acc[n][3],
                         af2[k8][0], af2[k8][1], af2[k8][2], af2[k8][3], bf.x, bf.y);
            }
        }
        #pragma unroll
        for (int n = 0; n < 8; ++n) {
            float2 o0 = make_float2(acc[n][0] + dvp[n].x, acc[n][1] + dvp[n].y);
            float2 o1 = make_float2(acc[n][2] + dvp[n].x, acc[n][3] + dvp[n].y);
            *reinterpret_cast<float2*>(out + (size_t)rowB * DD + 8 * n + 2 * t)       = o0;
            *reinterpret_cast<float2*>(out + (size_t)(rowB + 8) * DD + 8 * n + 2 * t) = o1;
        }
    }

    // ---- replay hygiene: last gemm block resets the counters ----
    __syncthreads();
    if (tid == 0) {
        unsigned v = atomicAdd(&g_done, 1u);
        if (v == 255u) {
            g_done = 0u;
            g_flag = 0u;
            __threadfence();
        }
    }
}

__global__ __launch_bounds__(256, 2) void fused_kernel(const float* __restrict__ x,
                                                       const float* __restrict__ W,
                                                       const float* __restrict__ B,
                                                       float* __restrict__ out) {
    extern __shared__ __align__(16) float sh[];
    if (blockIdx.x < 33)
        precompute_role(W, B, sh, blockIdx.x);
    else
        gemm_role(x, out, reinterpret_cast<unsigned*>(sh), blockIdx.x - 33);
}

extern "C" void kernel_launch(void* const* d_in, const int* in_sizes, int n_in,
                              void* d_out, int out_size) {
    const float* x = (const float*)d_in[0];
    const float* W = (const float*)d_in[1];
    const float* b = (const float*)d_in[2];
    float* out = (float*)d_out;

    const int smem_bytes = (64 * MS + 64) * 4;            // 18688 (covers both roles)
    cudaFuncSetAttribute(fused_kernel, cudaFuncAttributeMaxDynamicSharedMemorySize, smem_bytes);

    fused_kernel<<<289, 256, smem_bytes>>>(x, W, b, out);
}

// round 10
// speedup vs baseline: 2.6801x; 1.0014x over previous
#include <cuda_runtime.h>
#include <cuda_bf16.h>

#define NN 10
#define DD 64
#define MS 72

__device__ float g_M9[DD][DD];            // out = x @ g_M9 + g_dv9
__device__ float g_dv9[DD];
__device__ volatile unsigned g_flag;      // precompute-done counter (0..33)
__device__ unsigned g_done;               // gemm-block completion counter

__device__ __forceinline__ unsigned tf32_rna(float v) {
    unsigned u = __float_as_uint(v);
    return (u + 0x1000u) & 0xFFFFE000u;
}

__device__ __forceinline__ void mma_tf32(float& c0, float& c1, float& c2, float& c3,
                                         unsigned a0, unsigned a1, unsigned a2, unsigned a3,
                                         unsigned b0, unsigned b1) {
    asm volatile(
        "mma.sync.aligned.m16n8k8.row.col.f32.tf32.tf32.f32 "
        "{%0,%1,%2,%3}, {%4,%5,%6,%7}, {%8,%9}, {%0,%1,%2,%3};"
        : "+f"(c0), "+f"(c1), "+f"(c2), "+f"(c3)
        : "r"(a0), "r"(a1), "r"(a2), "r"(a3), "r"(b0), "r"(b1));
}

// ---- precompute role: blocks 0..32 -----------------------------------------
__device__ void precompute_role(const float* __restrict__ W,
                                const float* __restrict__ B,
                                float* sh, int bi) {
    float* rowsh = sh;                    // [NN][2][DD]
    float* red   = sh + NN * 2 * DD;      // [16][2][DD]
    const int tid  = threadIdx.x;
    const bool bias = (bi == 32);
    const int d0   = bi * 2;
    const int kk   = tid >> 4;
    const int hg   = tid & 15;
    const int rr   = tid >> 6;
    const int hh   = tid & 63;

    if (tid < 128)
        rowsh[(0 * 2 + rr) * DD + hh] = (!bias && (d0 + rr == hh)) ? 1.f : 0.f;
    __syncthreads();

    #pragma unroll
    for (int t = 1; t <= 9; ++t) {
        float extra = 0.f;
        if (tid < 128) {
            if (!bias) {
                extra = W[((size_t)t * DD + (d0 + rr)) * DD + hh];
            } else if (rr == 0) {
                #pragma unroll
                for (int f = 0; f < t; ++f)
                    extra += B[((size_t)f * NN + t) * DD + hh];
            }
        }

        float4 a0 = make_float4(0.f, 0.f, 0.f, 0.f);
        float4 a1 = make_float4(0.f, 0.f, 0.f, 0.f);

        #pragma unroll
        for (int f = 1; f < t; ++f) {
            const float* Wb = W + (((size_t)f * NN + t) * DD + kk * 4) * DD + hg * 4;
            float4 w0 = *reinterpret_cast<const float4*>(Wb + 0 * DD);
            float4 w1 = *reinterpret_cast<const float4*>(Wb + 1 * DD);
            float4 w2 = *reinterpret_cast<const float4*>(Wb + 2 * DD);
            float4 w3 = *reinterpret_cast<const float4*>(Wb + 3 * DD);
            float4 r0 = *reinterpret_cast<const float4*>(&rowsh[(f * 2 + 0) * DD + kk * 4]);
            float4 r1 = *reinterpret_cast<const float4*>(&rowsh[(f * 2 + 1) * DD + kk * 4]);
            a0.x += r0.x * w0.x + r0.y * w1.x + r0.z * w2.x + r0.w * w3.x;
            a0.y += r0.x * w0.y + r0.y * w1.y + r0.z * w2.y + r0.w * w3.y;
            a0.z += r0.x * w0.z + r0.y * w1.z + r0.z * w2.z + r0.w * w3.z;
            a0.w += r0.x * w0.w + r0.y * w1.w + r0.z * w2.w + r0.w * w3.w;
            a1.x += r1.x * w0.x + r1.y * w1.x + r1.z * w2.x + r1.w * w3.x;
            a1.y += r1.x * w0.y + r1.y * w1.y + r1.z * w2.y + r1.w * w3.y;
            a1.z += r1.x * w0.z + r1.y * w1.z + r1.z * w2.z + r1.w * w3.z;
            a1.w += r1.x * w0.w + r1.y * w1.w + r1.z * w2.w + r1.w * w3.w;
        }
        *reinterpret_cast<float4*>(&red[(kk * 2 + 0) * DD + hg * 4]) = a0;
        *reinterpret_cast<float4*>(&red[(kk * 2 + 1) * DD + hg * 4]) = a1;
        __syncthreads();

        if (tid < 128) {
            float s = extra;
            #pragma unroll
            for (int k2 = 0; k2 < 16; ++k2) s += red[(k2 * 2 + rr) * DD + hh];
            rowsh[(t * 2 + rr) * DD + hh] = s;
            if (t == 9) {
                if (!bias)        g_M9[d0 + rr][hh] = s;
                else if (rr == 0) g_dv9[hh] = s;
            }
        }
        __syncthreads();
    }

    __threadfence();
    __syncthreads();
    if (tid == 0) atomicAdd((unsigned*)&g_flag, 1u);
}

// ---- gemm role: blocks 33..288, 256 rows each -------------------------------
__device__ void gemm_role(const float* __restrict__ x, float* __restrict__ out,
                          unsigned* shb, int bid) {
    unsigned* Msm = shb;                                  // [64][MS]
    unsigned* xs2 = shb + 64 * MS;                        // [128][MS] tf32 half-2 rows
    float*    dvs = reinterpret_cast<float*>(xs2 + 128 * MS);
    const int tid  = threadIdx.x;
    const int w    = tid >> 5;
    const int lane = tid & 31;
    const int g    = lane >> 2;
    const int t    = lane & 3;
    const int R0   = bid * 256;
    const int rowA = R0 + w * 16 + g;                     // half-1 rows: rowA, rowA+8

    // ---- pre-wake 1: half-1 A fragments into registers (32 regs) ----
    unsigned af1[8][4];
    {
        const float2* a0 = reinterpret_cast<const float2*>(x + (size_t)rowA * DD);
        const float2* a1 = reinterpret_cast<const float2*>(x + (size_t)(rowA + 8) * DD);
        #pragma unroll
        for (int k8 = 0; k8 < 8; ++k8) {
            float2 v0 = a0[4 * k8 + t];
            float2 v1 = a1[4 * k8 + t];
            af1[k8][0] = tf32_rna(v0.x); af1[k8][2] = tf32_rna(v0.y);
            af1[k8][1] = tf32_rna(v1.x); af1[k8][3] = tf32_rna(v1.y);
        }
    }
    // ---- pre-wake 2: half-2 rows tf32-staged into shared (stride MS) ----
    {
        const int r    = tid >> 1;                        // local row 0..127
        const int half = tid & 1;                         // 32-col half
        const float4* src = reinterpret_cast<const float4*>(
            x + (size_t)(R0 + 128 + r) * DD + half * 32);
        #pragma unroll
        for (int i = 0; i < 8; ++i) {
            float4 v = src[i];
            uint4 u = make_uint4(tf32_rna(v.x), tf32_rna(v.y), tf32_rna(v.z), tf32_rna(v.w));
            *reinterpret_cast<uint4*>(&xs2[r * MS + half * 32 + 4 * i]) = u;
        }
    }

    // ---- wait: single-thread spin, rest park at the barrier ----
    if (tid == 0) {
        while (g_flag < 33u) __nanosleep(64);
        __threadfence();
    }
    __syncthreads();

    // ---- stage M^T + bias ----
    {
        const float* Mflat = &g_M9[0][0];
        #pragma unroll
        for (int i = 0; i < 16; ++i) {
            int idx = i * 256 + tid;
            int k = idx >> 6, n = idx & 63;
            Msm[n * MS + k] = tf32_rna(Mflat[idx]);
        }
        if (tid < 64) dvs[tid] = g_dv9[tid];
    }
    __syncthreads();

    float2 dvp[8];
    #pragma unroll
    for (int n = 0; n < 8; ++n)
        dvp[n] = *reinterpret_cast<const float2*>(&dvs[8 * n + 2 * t]);

    // ---- half 1: A from registers ----
    {
        float acc[8][4];
        #pragma unroll
        for (int n = 0; n < 8; ++n)
            #pragma unroll
            for (int c = 0; c < 4; ++c) acc[n][c] = 0.f;
        #pragma unroll
        for (int k8 = 0; k8 < 8; ++k8) {
            const int kcol = 8 * k8 + 2 * t;
            #pragma unroll
            for (int n = 0; n < 8; ++n) {
                uint2 bf = *reinterpret_cast<const uint2*>(&Msm[(8 * n + g) * MS + kcol]);
                mma_tf32(acc[n][0], acc[n][1], acc[n][2], acc[n][3],
                         af1[k8][0], af1[k8][1], af1[k8][2], af1[k8][3], bf.x, bf.y);
            }
        }
        #pragma unroll
        for (int n = 0; n < 8; ++n) {
            float2 o0 = make_float2(acc[n][0] + dvp[n].x, acc[n][1] + dvp[n].y);
            float2 o1 = make_float2(acc[n][2] + dvp[n].x, acc[n][3] + dvp[n].y);
            *reinterpret_cast<float2*>(out + (size_t)rowA * DD + 8 * n + 2 * t)       = o0;
            *reinterpret_cast<float2*>(out + (size_t)(rowA + 8) * DD + 8 * n + 2 * t) = o1;
        }
    }
    // ---- half 2: A fragments from shared (conflict-free LDS.64) ----
    {
        const int lr = w * 16 + g;                        // local rows lr, lr+8
        float acc[8][4];
        #pragma unroll
        for (int n = 0; n < 8; ++n)
            #pragma unroll
            for (int c = 0; c < 4; ++c) acc[n][c] = 0.f;
        #pragma unroll
        for (int k8 = 0; k8 < 8; ++k8) {
            const int kcol = 8 * k8 + 2 * t;
            uint2 a0 = *reinterpret_cast<const uint2*>(&xs2[lr * MS + kcol]);
            uint2 a1 = *reinterpret_cast<const uint2*>(&xs2[(lr + 8) * MS + kcol]);
            #pragma unroll
            for (int n = 0; n < 8; ++n) {
                uint2 bf = *reinterpret_cast<const uint2*>(&Msm[(8 * n + g) * MS + kcol]);
                mma_tf32(acc[n][0], acc[n][1], acc[n][2], acc[n][3],
                         a0.x, a1.x, a0.y, a1.y, bf.x, bf.y);
            }
        }
        const int rowB = R0 + 128 + lr;
        #pragma unroll
        for (int n = 0; n < 8; ++n) {
            float2 o0 = make_float2(acc[n][0] + dvp[n].x, acc[n][1] + dvp[n].y);
            float2 o1 = make_float2(acc[n][2] + dvp[n].x, acc[n][3] + dvp[n].y);
            *reinterpret_cast<float2*>(out + (size_t)rowB * DD + 8 * n + 2 * t)       = o0;
            *reinterpret_cast<float2*>(out + (size_t)(rowB + 8) * DD + 8 * n + 2 * t) = o1;
        }
    }

    // ---- replay hygiene: last gemm block resets the counters ----
    __syncthreads();
    if (tid == 0) {
        unsigned v = atomicAdd(&g_done, 1u);
        if (v == 255u) {
            g_done = 0u;
            g_flag = 0u;
            __threadfence();
        }
    }
}

__global__ __launch_bounds__(256, 2) void fused_kernel(const float* __restrict__ x,
                                                       const float* __restrict__ W,
                                                       const float* __restrict__ B,
                                                       float* __restrict__ out) {
    extern __shared__ __align__(16) float sh[];
    if (blockIdx.x < 33)
        precompute_role(W, B, sh, blockIdx.x);
    else
        gemm_role(x, out, reinterpret_cast<unsigned*>(sh), blockIdx.x - 33);
}

extern "C" void kernel_launch(void* const* d_in, const int* in_sizes, int n_in,
                              void* d_out, int out_size) {
    const float* x = (const float*)d_in[0];
    const float* W = (const float*)d_in[1];
    const float* b = (const float*)d_in[2];
    float* out = (float*)d_out;

    const int smem_bytes = (64 * MS + 128 * MS + 64) * 4;   // 55552
    cudaFuncSetAttribute(fused_kernel, cudaFuncAttributeMaxDynamicSharedMemorySize, smem_bytes);

    fused_kernel<<<289, 256, smem_bytes>>>(x, W, b, out);
}